// round 15
// baseline (speedup 1.0000x reference)
#include <cuda_runtime.h>
#include <cuda_fp16.h>
#include <cstdint>

#define B_    4096
#define LAT_  128
#define SEQ_  512
#define HID_  32
#define OUT_  64

#define NTHREAD 128       // 4 warps = 2 pair-groups; 1 warp per SMSP

typedef uint32_t u32;

__device__ __forceinline__ u32 tanh_h2(u32 x) {
    u32 r; asm("tanh.approx.f16x2 %0, %1;" : "=r"(r) : "r"(x)); return r;
}
__device__ __forceinline__ u32 packf2h2(float lo, float hi) {
    __half2 p = __floats2half2_rn(lo, hi);
    return *reinterpret_cast<u32*>(&p);
}
__device__ __forceinline__ __half2 asH2(u32 v) { return *reinterpret_cast<__half2*>(&v); }
__device__ __forceinline__ u32 asU32(__half2 v) { return *reinterpret_cast<u32*>(&v); }

__device__ __forceinline__ void mma_init(float d[4], const u32 a[4], const u32 b[2],
                                         float c0, float c1) {
    asm volatile("mma.sync.aligned.m16n8k16.row.col.f32.f16.f16.f32 "
                 "{%0,%1,%2,%3}, {%4,%5,%6,%7}, {%8,%9}, {%10,%11,%12,%13};"
                 : "=f"(d[0]), "=f"(d[1]), "=f"(d[2]), "=f"(d[3])
                 : "r"(a[0]), "r"(a[1]), "r"(a[2]), "r"(a[3]),
                   "r"(b[0]), "r"(b[1]),
                   "f"(c0), "f"(c1), "f"(c0), "f"(c1));
}
__device__ __forceinline__ void mma_acc(float d[4], const u32 a[4], const u32 b[2]) {
    asm volatile("mma.sync.aligned.m16n8k16.row.col.f32.f16.f16.f32 "
                 "{%0,%1,%2,%3}, {%4,%5,%6,%7}, {%8,%9}, {%0,%1,%2,%3};"
                 : "+f"(d[0]), "+f"(d[1]), "+f"(d[2]), "+f"(d[3])
                 : "r"(a[0]), "r"(a[1]), "r"(a[2]), "r"(a[3]),
                   "r"(b[0]), "r"(b[1]));
}
#define PBAR(id) asm volatile("bar.sync %0, 64;" :: "r"(id) : "memory")

__global__ void __launch_bounds__(NTHREAD, 1)
lstm_pair_kernel(const float* __restrict__ z,
                 const float* __restrict__ init_W,
                 const float* __restrict__ init_b,
                 const float* __restrict__ W_hh,
                 const float* __restrict__ b_ih,
                 const float* __restrict__ b_hh,
                 const float* __restrict__ out_W,
                 const float* __restrict__ out_b,
                 float* __restrict__ y)
{
    __shared__ __align__(16) __half hbuf[32][32];        // h0 staging (2 KB)
    __shared__ __align__(16) uint4  xbuf[2][2][2][32];   // exchange (4 KB)

    const int tid = threadIdx.x;
    const int w   = tid >> 5;
    const int l   = tid & 31;
    const int g   = l >> 2;
    const int tig = l & 3;
    const int p   = w >> 1;        // pair-group: rows [p*16, p*16+16) of CTA
    const int r   = w & 1;         // role: gate cols / k-slice [16r, 16r+16)
    const int cta = blockIdx.x;

    // ======== static weight fragments (registers) ========
    // i/f/o pre-scaled 0.5: sigmoid(x) = 0.5*tanh(0.5x) + 0.5
    u32   Bg[4][2][2][2];    // [gate][ntile'][khalf][reg] = 32 regs
    float bg[4][2][2];       // f32 biases as MMA C       = 16 regs
#pragma unroll
    for (int G = 0; G < 4; G++) {
        const float sc = (G == 2) ? 1.0f : 0.5f;
#pragma unroll
        for (int ti = 0; ti < 2; ti++) {
            const int row = G * 32 + 16 * r + 8 * ti + g;
#pragma unroll
            for (int s = 0; s < 2; s++)
#pragma unroll
                for (int hh = 0; hh < 2; hh++) {
                    const int k = 2 * tig + 16 * s + 8 * hh;
                    float2 v = *reinterpret_cast<const float2*>(W_hh + row * HID_ + k);
                    Bg[G][ti][s][hh] = packf2h2(v.x * sc, v.y * sc);
                }
            const int n0 = G * 32 + 16 * r + 8 * ti + 2 * tig;
            bg[G][ti][0] = (b_ih[n0]     + b_hh[n0])     * sc;
            bg[G][ti][1] = (b_ih[n0 + 1] + b_hh[n0 + 1]) * sc;
        }
    }
    u32   Bp[4][2][2];       // proj cols [32r, 32r+32) = 16 regs
    float pb[4][2];          //                            8 regs
#pragma unroll
    for (int ti = 0; ti < 4; ti++) {
        const int row = (4 * r + ti) * 8 + g;
#pragma unroll
        for (int s = 0; s < 2; s++)
#pragma unroll
            for (int hh = 0; hh < 2; hh++) {
                const int k = 2 * tig + 16 * s + 8 * hh;
                float2 v = *reinterpret_cast<const float2*>(out_W + row * HID_ + k);
                Bp[ti][s][hh] = packf2h2(v.x, v.y);
            }
        const int n0 = (4 * r + ti) * 8 + 2 * tig;
        pb[ti][0] = out_b[n0];
        pb[ti][1] = out_b[n0 + 1];
    }

    // ======== h0 = z @ init_W^T + init_b -> hbuf (fp16) ========
    {
        const int row = tid >> 2;            // 0..31
        const int c0  = (tid & 3) * 8;       // 8 H-cols per thread
        float acc[8];
#pragma unroll
        for (int cc = 0; cc < 8; cc++) acc[cc] = init_b[c0 + cc];
        const float* zr = z + ((size_t)cta * 32 + row) * LAT_;
        for (int k = 0; k < LAT_; k++) {
            const float zk = zr[k];
#pragma unroll
            for (int cc = 0; cc < 8; cc++)
                acc[cc] = fmaf(zk, init_W[(c0 + cc) * LAT_ + k], acc[cc]);
        }
#pragma unroll
        for (int cc = 0; cc < 8; cc += 2)
            *reinterpret_cast<__half2*>(&hbuf[row][c0 + cc]) =
                __floats2half2_rn(acc[cc], acc[cc + 1]);
    }
    __syncthreads();

    // ======== build initial A fragments from hbuf (one-time, LDS.32) ======
    // A0 = k-cols [0,16), A1 = k-cols [16,32); m16 rows = [p*16, p*16+16)
    u32 A0[4], A1[4];
#pragma unroll
    for (int s = 0; s < 2; s++) {
        u32* Af = s ? A1 : A0;
        const int rbase = p * 16;
        Af[0] = asU32(*reinterpret_cast<__half2*>(&hbuf[rbase + g    ][16 * s + 2 * tig]));
        Af[1] = asU32(*reinterpret_cast<__half2*>(&hbuf[rbase + g + 8][16 * s + 2 * tig]));
        Af[2] = asU32(*reinterpret_cast<__half2*>(&hbuf[rbase + g    ][16 * s + 8 + 2 * tig]));
        Af[3] = asU32(*reinterpret_cast<__half2*>(&hbuf[rbase + g + 8][16 * s + 8 + 2 * tig]));
    }

    float cst[8];
#pragma unroll
    for (int i = 0; i < 8; i++) cst[i] = 0.0f;

    const __half2 h05 = __floats2half2_rn(0.5f, 0.5f);
    float* ybase = y + ((size_t)cta * 32 + p * 16 + g) * (size_t)SEQ_ * OUT_;
    const int barid = 1 + p;

    // ======== recurrence: 2-warp group, direct fragment exchange ==========
    // Loop-top invariant: {A0,A1} = h_t. proj(A) -> y[t-1] (post-exchange
    // position per R7/R14 finding), gates(A) -> own k16-frag of h_{t+1},
    // STS.128 own / bar 64 / LDS.128 partner.
#pragma unroll 1
    for (int t = 0; t < SEQ_; t++) {
        // ---- y[t-1] = proj(h_t) ----
        if (t > 0) {
            float dp[4][4];
#pragma unroll
            for (int ti = 0; ti < 4; ti++) {
                mma_init(dp[ti], A0, Bp[ti][0], pb[ti][0], pb[ti][1]);
                mma_acc (dp[ti], A1, Bp[ti][1]);
            }
#pragma unroll
            for (int ti = 0; ti < 4; ti++) {
                const int col = (4 * r + ti) * 8 + 2 * tig;
                float* yr0 = ybase + (size_t)(t - 1) * OUT_ + col;
                float* yr1 = yr0 + (size_t)8 * SEQ_ * OUT_;
                *reinterpret_cast<float2*>(yr0) = make_float2(dp[ti][0], dp[ti][1]);
                *reinterpret_cast<float2*>(yr1) = make_float2(dp[ti][2], dp[ti][3]);
            }
        }

        // ---- gates for own 16 h-cols: 2 n8-tiles x 4 gates ----
        u32 An[4];
#pragma unroll
        for (int ti = 0; ti < 2; ti++) {
            float dg[4][4];
#pragma unroll
            for (int G = 0; G < 4; G++) {
                mma_init(dg[G], A0, Bg[G][ti][0], bg[G][ti][0], bg[G][ti][1]);
                mma_acc (dg[G], A1, Bg[G][ti][1]);
            }
#pragma unroll
            for (int rr = 0; rr < 2; rr++) {
                const int d0 = rr * 2, d1 = rr * 2 + 1;
                const int ci = ti * 4 + rr * 2;
                u32 tI = tanh_h2(packf2h2(dg[0][d0], dg[0][d1]));
                u32 tF = tanh_h2(packf2h2(dg[1][d0], dg[1][d1]));
                u32 tG = tanh_h2(packf2h2(dg[2][d0], dg[2][d1]));
                u32 tO = tanh_h2(packf2h2(dg[3][d0], dg[3][d1]));
                __half2 I2 = __hfma2(asH2(tI), h05, h05);
                __half2 F2 = __hfma2(asH2(tF), h05, h05);
                __half2 O2 = __hfma2(asH2(tO), h05, h05);
                __half2 G2 = asH2(tG);
                float I0 = __low2float(I2), I1 = __high2float(I2);
                float F0 = __low2float(F2), F1 = __high2float(F2);
                float G0 = __low2float(G2), G1 = __high2float(G2);
                cst[ci]     = fmaf(F0, cst[ci],     I0 * G0);
                cst[ci + 1] = fmaf(F1, cst[ci + 1], I1 * G1);
                u32 tC = tanh_h2(packf2h2(cst[ci], cst[ci + 1]));
                An[ti * 2 + rr] = asU32(__hmul2(O2, asH2(tC)));
            }
        }

        // ---- exchange: own k16-frag out, partner's in (double-buffered) ----
        const int pb_ = t & 1;
        xbuf[pb_][p][r][l] = make_uint4(An[0], An[1], An[2], An[3]);
        PBAR(barid);
        uint4 pv = xbuf[pb_][p][r ^ 1][l];
        if (r == 0) {
            A0[0] = An[0]; A0[1] = An[1]; A0[2] = An[2]; A0[3] = An[3];
            A1[0] = pv.x;  A1[1] = pv.y;  A1[2] = pv.z;  A1[3] = pv.w;
        } else {
            A1[0] = An[0]; A1[1] = An[1]; A1[2] = An[2]; A1[3] = An[3];
            A0[0] = pv.x;  A0[1] = pv.y;  A0[2] = pv.z;  A0[3] = pv.w;
        }
    }

    // ======== epilogue: y[511] = proj(h_512) ========
    {
        float dp[4][4];
#pragma unroll
        for (int ti = 0; ti < 4; ti++) {
            mma_init(dp[ti], A0, Bp[ti][0], pb[ti][0], pb[ti][1]);
            mma_acc (dp[ti], A1, Bp[ti][1]);
        }
#pragma unroll
        for (int ti = 0; ti < 4; ti++) {
            const int col = (4 * r + ti) * 8 + 2 * tig;
            float* yr0 = ybase + (size_t)(SEQ_ - 1) * OUT_ + col;
            float* yr1 = yr0 + (size_t)8 * SEQ_ * OUT_;
            *reinterpret_cast<float2*>(yr0) = make_float2(dp[ti][0], dp[ti][1]);
            *reinterpret_cast<float2*>(yr1) = make_float2(dp[ti][2], dp[ti][3]);
        }
    }
}

extern "C" void kernel_launch(void* const* d_in, const int* in_sizes, int n_in,
                              void* d_out, int out_size)
{
    // metadata order: z, init_W, init_b, W_ih, W_hh, b_ih, b_hh, out_W, out_b
    const float* z      = (const float*)d_in[0];
    const float* init_W = (const float*)d_in[1];
    const float* init_b = (const float*)d_in[2];
    // d_in[3] = W_ih: unused (input sequence is all zeros)
    const float* W_hh   = (const float*)d_in[4];
    const float* b_ih   = (const float*)d_in[5];
    const float* b_hh   = (const float*)d_in[6];
    const float* out_W  = (const float*)d_in[7];
    const float* out_b  = (const float*)d_in[8];
    float* y            = (float*)d_out;

    lstm_pair_kernel<<<B_ / 32, NTHREAD>>>(   // 128 CTAs x 128 thr
        z, init_W, init_b, W_hh, b_ih, b_hh, out_W, out_b, y);
}

// round 16
// speedup vs baseline: 1.5142x; 1.5142x over previous
#include <cuda_runtime.h>
#include <cuda_fp16.h>
#include <cstdint>

#define B_    4096
#define LAT_  128
#define SEQ_  512
#define HID_  32
#define OUT_  64

#define ROWS_PER_CTA 32
#define NTHREAD 256
#define ROWB 40   // h tile row stride in halves (80B, ldmatrix-friendly)

typedef uint32_t u32;

__device__ __forceinline__ float tanha(float x) {
    float r; asm("tanh.approx.f32 %0, %1;" : "=f"(r) : "f"(x)); return r;
}
__device__ __forceinline__ void ldsm4(u32 r[4], u32 saddr) {
    asm volatile("ldmatrix.sync.aligned.m8n8.x4.shared.b16 {%0,%1,%2,%3}, [%4];"
                 : "=r"(r[0]), "=r"(r[1]), "=r"(r[2]), "=r"(r[3])
                 : "r"(saddr));
}
__device__ __forceinline__ void mma_init(float d[4], const u32 a[4], const u32 b[2],
                                         float c0, float c1) {
    asm volatile("mma.sync.aligned.m16n8k16.row.col.f32.f16.f16.f32 "
                 "{%0,%1,%2,%3}, {%4,%5,%6,%7}, {%8,%9}, {%10,%11,%12,%13};"
                 : "=f"(d[0]), "=f"(d[1]), "=f"(d[2]), "=f"(d[3])
                 : "r"(a[0]), "r"(a[1]), "r"(a[2]), "r"(a[3]),
                   "r"(b[0]), "r"(b[1]),
                   "f"(c0), "f"(c1), "f"(c0), "f"(c1));
}
__device__ __forceinline__ void mma_acc(float d[4], const u32 a[4], const u32 b[2]) {
    asm volatile("mma.sync.aligned.m16n8k16.row.col.f32.f16.f16.f32 "
                 "{%0,%1,%2,%3}, {%4,%5,%6,%7}, {%8,%9}, {%0,%1,%2,%3};"
                 : "+f"(d[0]), "+f"(d[1]), "+f"(d[2]), "+f"(d[3])
                 : "r"(a[0]), "r"(a[1]), "r"(a[2]), "r"(a[3]),
                   "r"(b[0]), "r"(b[1]));
}
__device__ __forceinline__ u32 packh2(float lo, float hi) {
    __half2 p = __floats2half2_rn(lo, hi);
    return *reinterpret_cast<u32*>(&p);
}
#define GBAR(id) asm volatile("bar.sync %0, 128;" :: "r"(id) : "memory")

__global__ void __launch_bounds__(NTHREAD, 1)
lstm_mma_kernel(const float* __restrict__ z,
                const float* __restrict__ init_W,
                const float* __restrict__ init_b,
                const float* __restrict__ W_hh,
                const float* __restrict__ b_ih,
                const float* __restrict__ b_hh,
                const float* __restrict__ out_W,
                const float* __restrict__ out_b,
                float* __restrict__ y)
{
    __shared__ __align__(16) __half hbuf[2][ROWS_PER_CTA][ROWB];   // 5120 B

    const int tid = threadIdx.x;
    const int w   = tid >> 5;
    const int l   = tid & 31;
    const int g   = l >> 2;
    const int tig = l & 3;
    const int gid = w >> 2;            // row-group: 0 -> rows 0-15, 1 -> 16-31
    const int wg  = w & 3;             // warp within group: n-slice
    const int cta = blockIdx.x;

    // ---- static weight fragments (fp16 B operands) ----
    // i/f/o gates pre-scaled by 0.5 so sigmoid(x) = 0.5*tanh(arg)+0.5
    u32 Bg[4][2][2];
    float bg[4][2];
#pragma unroll
    for (int G = 0; G < 4; G++) {
        const float sc = (G == 2) ? 1.0f : 0.5f;
        const int row = G * 32 + 8 * wg + g;
#pragma unroll
        for (int s = 0; s < 2; s++)
#pragma unroll
            for (int hh = 0; hh < 2; hh++) {
                const int k = 2 * tig + 16 * s + 8 * hh;
                float2 v = *reinterpret_cast<const float2*>(W_hh + row * HID_ + k);
                Bg[G][s][hh] = packh2(v.x * sc, v.y * sc);
            }
        const int n0 = G * 32 + 8 * wg + 2 * tig;
        bg[G][0] = (b_ih[n0]     + b_hh[n0])     * sc;
        bg[G][1] = (b_ih[n0 + 1] + b_hh[n0 + 1]) * sc;
    }
    u32 Bp[2][2][2];
    float pb[2][2];
#pragma unroll
    for (int ti = 0; ti < 2; ti++) {
        const int row = (wg + 4 * ti) * 8 + g;
#pragma unroll
        for (int s = 0; s < 2; s++)
#pragma unroll
            for (int hh = 0; hh < 2; hh++) {
                const int k = 2 * tig + 16 * s + 8 * hh;
                float2 v = *reinterpret_cast<const float2*>(out_W + row * HID_ + k);
                Bp[ti][s][hh] = packh2(v.x, v.y);
            }
        const int n0 = (wg + 4 * ti) * 8 + 2 * tig;
        pb[ti][0] = out_b[n0];
        pb[ti][1] = out_b[n0 + 1];
    }

    // ---- h0 = z @ init_W^T + init_b -> hbuf[0] (fp16) ----
    {
        const int row = tid >> 3;            // 0..31
        const int c0  = (tid & 7) * 4;       // 4 H-cols per thread
        float acc[4];
#pragma unroll
        for (int cc = 0; cc < 4; cc++) acc[cc] = init_b[c0 + cc];
        const float* zr = z + ((size_t)cta * ROWS_PER_CTA + row) * LAT_;
        for (int k = 0; k < LAT_; k++) {
            const float zk = zr[k];
#pragma unroll
            for (int cc = 0; cc < 4; cc++)
                acc[cc] = fmaf(zk, init_W[(c0 + cc) * LAT_ + k], acc[cc]);
        }
#pragma unroll
        for (int cc = 0; cc < 4; cc++)
            hbuf[0][row][c0 + cc] = __float2half(acc[cc]);
    }

    float cst[4];
#pragma unroll
    for (int i = 0; i < 4; i++) cst[i] = 0.0f;

    u32 hbase[2];
    hbase[0] = (u32)__cvta_generic_to_shared(&hbuf[0][0][0]);
    hbase[1] = (u32)__cvta_generic_to_shared(&hbuf[1][0][0]);
    const u32 grp_off = (u32)(gid * 16 * ROWB * 2);
    const u32 off_ld  = (u32)(((l & 15) * ROWB + (l >> 4) * 8) * 2);

    GBAR(1 + gid);

    // ---- calibrated anti-phase offset: group 1 runs a ~384-cycle dependent
    // MUFU chain ONCE, so its tail phase lands opposite group 0's on each
    // SMSP and the MUFU port stays continuously fed (A-tail || B-spine). ----
    if (gid == 1) {
        float d = 1.5f + (float)l;
#pragma unroll
        for (int i = 0; i < 24; i++)
            asm volatile("rcp.approx.f32 %0, %0;" : "+f"(d));
        // opaque sink: never true at runtime, keeps the chain live
        if (d == 12345.678f) hbuf[0][0][0] = __float2half(d);
    }

    // prime A fragments from h0 (this group's 16 rows)
    u32 A[2][4];
#pragma unroll
    for (int s = 0; s < 2; s++)
        ldsm4(A[s], hbase[0] + grp_off + off_ld + (u32)(s * 32));

    float* ybase0 = y + ((size_t)cta * ROWS_PER_CTA + gid * 16 + g)
                        * (size_t)SEQ_ * OUT_;

#pragma unroll 1
    for (int t = 0; t < SEQ_; t++) {
        const int wb = (t + 1) & 1;

        // ---- gates = h_t @ W_hh^T + bias (i/f/o pre-scaled 0.5) ----
        float dg[4][4];
#pragma unroll
        for (int G = 0; G < 4; G++) {
            mma_init(dg[G], A[0], Bg[G][0], bg[G][0], bg[G][1]);
            mma_acc (dg[G], A[1], Bg[G][1]);
        }

        // ---- nonlinearities: 4 cells/lane, 5 MUFU.TANH each ----
        float hv[2][2];
#pragma unroll
        for (int rr = 0; rr < 2; rr++)
#pragma unroll
            for (int cc = 0; cc < 2; cc++) {
                const int di = rr * 2 + cc;
                float I = fmaf(tanha(dg[0][di]), 0.5f, 0.5f);
                float F = fmaf(tanha(dg[1][di]), 0.5f, 0.5f);
                float G_ = tanha(dg[2][di]);
                float O = fmaf(tanha(dg[3][di]), 0.5f, 0.5f);
                cst[di] = fmaf(F, cst[di], I * G_);
                hv[rr][cc] = O * tanha(cst[di]);
            }

        // ---- publish h_{t+1} (fp16) ----
#pragma unroll
        for (int rr = 0; rr < 2; rr++)
            *reinterpret_cast<__half2*>(
                &hbuf[wb][gid * 16 + g + rr * 8][8 * wg + 2 * tig]) =
                __floats2half2_rn(hv[rr][0], hv[rr][1]);
        GBAR(1 + gid);

        // ---- reload A: serves proj(t) AND gates(t+1) ----
#pragma unroll
        for (int s = 0; s < 2; s++)
            ldsm4(A[s], hbase[wb] + grp_off + off_ld + (u32)(s * 32));

        // ---- y_t = h_{t+1} @ out_W^T + out_b ----
        float dp[2][4];
#pragma unroll
        for (int ti = 0; ti < 2; ti++) {
            mma_init(dp[ti], A[0], Bp[ti][0], pb[ti][0], pb[ti][1]);
            mma_acc (dp[ti], A[1], Bp[ti][1]);
        }
#pragma unroll
        for (int ti = 0; ti < 2; ti++) {
            const int col = (wg + 4 * ti) * 8 + 2 * tig;
            float* yr0 = ybase0 + (size_t)t * OUT_ + col;
            float* yr1 = yr0 + (size_t)8 * SEQ_ * OUT_;
            *reinterpret_cast<float2*>(yr0) = make_float2(dp[ti][0], dp[ti][1]);
            *reinterpret_cast<float2*>(yr1) = make_float2(dp[ti][2], dp[ti][3]);
        }
    }
}

extern "C" void kernel_launch(void* const* d_in, const int* in_sizes, int n_in,
                              void* d_out, int out_size)
{
    // metadata order: z, init_W, init_b, W_ih, W_hh, b_ih, b_hh, out_W, out_b
    const float* z      = (const float*)d_in[0];
    const float* init_W = (const float*)d_in[1];
    const float* init_b = (const float*)d_in[2];
    // d_in[3] = W_ih: unused (input sequence is all zeros)
    const float* W_hh   = (const float*)d_in[4];
    const float* b_ih   = (const float*)d_in[5];
    const float* b_hh   = (const float*)d_in[6];
    const float* out_W  = (const float*)d_in[7];
    const float* out_b  = (const float*)d_in[8];
    float* y            = (float*)d_out;

    lstm_mma_kernel<<<B_ / ROWS_PER_CTA, NTHREAD>>>(   // 128 CTAs x 256 thr
        z, init_W, init_b, W_hh, b_ih, b_hh, out_W, out_b, y);
}

// round 17
// speedup vs baseline: 1.5447x; 1.0201x over previous
#include <cuda_runtime.h>
#include <cuda_fp16.h>
#include <cstdint>

#define B_    4096
#define LAT_  128
#define SEQ_  512
#define HID_  32
#define OUT_  64

#define ROWS_PER_CTA 32
#define NTHREAD 256
#define ROWB 40   // h tile row stride in halves (80B, ldmatrix-friendly)

typedef uint32_t u32;

__device__ __forceinline__ float tanha(float x) {
    float r; asm("tanh.approx.f32 %0, %1;" : "=f"(r) : "f"(x)); return r;
}
__device__ __forceinline__ void ldsm4(u32 r[4], u32 saddr) {
    asm volatile("ldmatrix.sync.aligned.m8n8.x4.shared.b16 {%0,%1,%2,%3}, [%4];"
                 : "=r"(r[0]), "=r"(r[1]), "=r"(r[2]), "=r"(r[3])
                 : "r"(saddr));
}
__device__ __forceinline__ void mma_init(float d[4], const u32 a[4], const u32 b[2],
                                         float c0, float c1) {
    asm volatile("mma.sync.aligned.m16n8k16.row.col.f32.f16.f16.f32 "
                 "{%0,%1,%2,%3}, {%4,%5,%6,%7}, {%8,%9}, {%10,%11,%12,%13};"
                 : "=f"(d[0]), "=f"(d[1]), "=f"(d[2]), "=f"(d[3])
                 : "r"(a[0]), "r"(a[1]), "r"(a[2]), "r"(a[3]),
                   "r"(b[0]), "r"(b[1]),
                   "f"(c0), "f"(c1), "f"(c0), "f"(c1));
}
__device__ __forceinline__ void mma_acc(float d[4], const u32 a[4], const u32 b[2]) {
    asm volatile("mma.sync.aligned.m16n8k16.row.col.f32.f16.f16.f32 "
                 "{%0,%1,%2,%3}, {%4,%5,%6,%7}, {%8,%9}, {%0,%1,%2,%3};"
                 : "+f"(d[0]), "+f"(d[1]), "+f"(d[2]), "+f"(d[3])
                 : "r"(a[0]), "r"(a[1]), "r"(a[2]), "r"(a[3]),
                   "r"(b[0]), "r"(b[1]));
}
__device__ __forceinline__ u32 packh2(float lo, float hi) {
    __half2 p = __floats2half2_rn(lo, hi);
    return *reinterpret_cast<u32*>(&p);
}
#define GBAR(id) asm volatile("bar.sync %0, 128;" :: "r"(id) : "memory")

__global__ void __launch_bounds__(NTHREAD, 1)
lstm_mma_kernel(const float* __restrict__ z,
                const float* __restrict__ init_W,
                const float* __restrict__ init_b,
                const float* __restrict__ W_hh,
                const float* __restrict__ b_ih,
                const float* __restrict__ b_hh,
                const float* __restrict__ out_W,
                const float* __restrict__ out_b,
                float* __restrict__ y)
{
    __shared__ __align__(16) __half hbuf[2][ROWS_PER_CTA][ROWB];   // 5120 B

    const int tid = threadIdx.x;
    const int w   = tid >> 5;
    const int l   = tid & 31;
    const int g   = l >> 2;
    const int tig = l & 3;
    const int gid = w >> 2;            // row-group: 0 -> rows 0-15, 1 -> 16-31
    const int wg  = w & 3;             // warp within group: n-slice
    const int cta = blockIdx.x;

    // ---- static weight fragments (fp16 B operands) ----
    // i/f/o gates pre-scaled by 0.5 so sigmoid(x) = 0.5*tanh(arg)+0.5
    u32 Bg[4][2][2];
    float bg[4][2];
#pragma unroll
    for (int G = 0; G < 4; G++) {
        const float sc = (G == 2) ? 1.0f : 0.5f;
        const int row = G * 32 + 8 * wg + g;
#pragma unroll
        for (int s = 0; s < 2; s++)
#pragma unroll
            for (int hh = 0; hh < 2; hh++) {
                const int k = 2 * tig + 16 * s + 8 * hh;
                float2 v = *reinterpret_cast<const float2*>(W_hh + row * HID_ + k);
                Bg[G][s][hh] = packh2(v.x * sc, v.y * sc);
            }
        const int n0 = G * 32 + 8 * wg + 2 * tig;
        bg[G][0] = (b_ih[n0]     + b_hh[n0])     * sc;
        bg[G][1] = (b_ih[n0 + 1] + b_hh[n0 + 1]) * sc;
    }
    u32 Bp[2][2][2];
    float pb[2][2];
#pragma unroll
    for (int ti = 0; ti < 2; ti++) {
        const int row = (wg + 4 * ti) * 8 + g;
#pragma unroll
        for (int s = 0; s < 2; s++)
#pragma unroll
            for (int hh = 0; hh < 2; hh++) {
                const int k = 2 * tig + 16 * s + 8 * hh;
                float2 v = *reinterpret_cast<const float2*>(out_W + row * HID_ + k);
                Bp[ti][s][hh] = packh2(v.x, v.y);
            }
        const int n0 = (wg + 4 * ti) * 8 + 2 * tig;
        pb[ti][0] = out_b[n0];
        pb[ti][1] = out_b[n0 + 1];
    }

    // ---- h0 = z @ init_W^T + init_b -> hbuf[0] (fp16) ----
    {
        const int row = tid >> 3;            // 0..31
        const int c0  = (tid & 7) * 4;       // 4 H-cols per thread
        float acc[4];
#pragma unroll
        for (int cc = 0; cc < 4; cc++) acc[cc] = init_b[c0 + cc];
        const float* zr = z + ((size_t)cta * ROWS_PER_CTA + row) * LAT_;
        for (int k = 0; k < LAT_; k++) {
            const float zk = zr[k];
#pragma unroll
            for (int cc = 0; cc < 4; cc++)
                acc[cc] = fmaf(zk, init_W[(c0 + cc) * LAT_ + k], acc[cc]);
        }
#pragma unroll
        for (int cc = 0; cc < 4; cc++)
            hbuf[0][row][c0 + cc] = __float2half(acc[cc]);
    }

    float cst[4];
#pragma unroll
    for (int i = 0; i < 4; i++) cst[i] = 0.0f;

    u32 hbase[2];
    hbase[0] = (u32)__cvta_generic_to_shared(&hbuf[0][0][0]);
    hbase[1] = (u32)__cvta_generic_to_shared(&hbuf[1][0][0]);
    const u32 grp_off = (u32)(gid * 16 * ROWB * 2);
    const u32 off_ld  = (u32)(((l & 15) * ROWB + (l >> 4) * 8) * 2);

    GBAR(1 + gid);

    // prime A fragments from h0 (this group's 16 rows)
    u32 A[2][4];
#pragma unroll
    for (int s = 0; s < 2; s++)
        ldsm4(A[s], hbase[0] + grp_off + off_ld + (u32)(s * 32));

    float* ybase0 = y + ((size_t)cta * ROWS_PER_CTA + gid * 16 + g)
                        * (size_t)SEQ_ * OUT_;

    // Loop-top invariant: A = fragments of h_t.
    //   gates(A) -> h_{t+1}; STS; bar.
    //   Then, in the BAR defer-blocking shadow (before the first barrier-
    //   dependent consumer, the ldsm): proj(A)=proj(h_t)=y[t-1] + its STGs —
    //   register-only work that issues while the barrier pends.
#pragma unroll 1
    for (int t = 0; t < SEQ_; t++) {
        const int wb = (t + 1) & 1;

        // ---- gates = h_t @ W_hh^T + bias (i/f/o pre-scaled 0.5) ----
        float dg[4][4];
#pragma unroll
        for (int G = 0; G < 4; G++) {
            mma_init(dg[G], A[0], Bg[G][0], bg[G][0], bg[G][1]);
            mma_acc (dg[G], A[1], Bg[G][1]);
        }

        // ---- nonlinearities: 4 cells/lane, 5 MUFU.TANH each ----
        float hv[2][2];
#pragma unroll
        for (int rr = 0; rr < 2; rr++)
#pragma unroll
            for (int cc = 0; cc < 2; cc++) {
                const int di = rr * 2 + cc;
                float I = fmaf(tanha(dg[0][di]), 0.5f, 0.5f);
                float F = fmaf(tanha(dg[1][di]), 0.5f, 0.5f);
                float G_ = tanha(dg[2][di]);
                float O = fmaf(tanha(dg[3][di]), 0.5f, 0.5f);
                cst[di] = fmaf(F, cst[di], I * G_);
                hv[rr][cc] = O * tanha(cst[di]);
            }

        // ---- publish h_{t+1} (fp16) ----
#pragma unroll
        for (int rr = 0; rr < 2; rr++)
            *reinterpret_cast<__half2*>(
                &hbuf[wb][gid * 16 + g + rr * 8][8 * wg + 2 * tig]) =
                __floats2half2_rn(hv[rr][0], hv[rr][1]);
        GBAR(1 + gid);

        // ---- bar-shadow work: y[t-1] = proj(h_t) from the OLD A ----
        float dp[2][4];
#pragma unroll
        for (int ti = 0; ti < 2; ti++) {
            mma_init(dp[ti], A[0], Bp[ti][0], pb[ti][0], pb[ti][1]);
            mma_acc (dp[ti], A[1], Bp[ti][1]);
        }
        if (t > 0) {
#pragma unroll
            for (int ti = 0; ti < 2; ti++) {
                const int col = (wg + 4 * ti) * 8 + 2 * tig;
                float* yr0 = ybase0 + (size_t)(t - 1) * OUT_ + col;
                float* yr1 = yr0 + (size_t)8 * SEQ_ * OUT_;
                *reinterpret_cast<float2*>(yr0) = make_float2(dp[ti][0], dp[ti][1]);
                *reinterpret_cast<float2*>(yr1) = make_float2(dp[ti][2], dp[ti][3]);
            }
        }

        // ---- first barrier-dependent consumer: reload A <- h_{t+1} ----
#pragma unroll
        for (int s = 0; s < 2; s++)
            ldsm4(A[s], hbase[wb] + grp_off + off_ld + (u32)(s * 32));
    }

    // ---- epilogue: y[511] = proj(h_512); A holds h_512 ----
    {
        float dp[2][4];
#pragma unroll
        for (int ti = 0; ti < 2; ti++) {
            mma_init(dp[ti], A[0], Bp[ti][0], pb[ti][0], pb[ti][1]);
            mma_acc (dp[ti], A[1], Bp[ti][1]);
        }
#pragma unroll
        for (int ti = 0; ti < 2; ti++) {
            const int col = (wg + 4 * ti) * 8 + 2 * tig;
            float* yr0 = ybase0 + (size_t)(SEQ_ - 1) * OUT_ + col;
            float* yr1 = yr0 + (size_t)8 * SEQ_ * OUT_;
            *reinterpret_cast<float2*>(yr0) = make_float2(dp[ti][0], dp[ti][1]);
            *reinterpret_cast<float2*>(yr1) = make_float2(dp[ti][2], dp[ti][3]);
        }
    }
}

extern "C" void kernel_launch(void* const* d_in, const int* in_sizes, int n_in,
                              void* d_out, int out_size)
{
    // metadata order: z, init_W, init_b, W_ih, W_hh, b_ih, b_hh, out_W, out_b
    const float* z      = (const float*)d_in[0];
    const float* init_W = (const float*)d_in[1];
    const float* init_b = (const float*)d_in[2];
    // d_in[3] = W_ih: unused (input sequence is all zeros)
    const float* W_hh   = (const float*)d_in[4];
    const float* b_ih   = (const float*)d_in[5];
    const float* b_hh   = (const float*)d_in[6];
    const float* out_W  = (const float*)d_in[7];
    const float* out_b  = (const float*)d_in[8];
    float* y            = (float*)d_out;

    lstm_mma_kernel<<<B_ / ROWS_PER_CTA, NTHREAD>>>(   // 128 CTAs x 256 thr
        z, init_W, init_b, W_hh, b_ih, b_hh, out_W, out_b, y);
}